// round 10
// baseline (speedup 1.0000x reference)
#include <cuda_runtime.h>
#include <cstddef>

#define NEGV -1000000000.0f
#define HDIM 128
#define NMAX 12288

// per-node partials: g_p[n].x = h[n].W[0:128), g_p[n].y = h[n].W[128:256)
__device__ float2 g_p[NMAX];

// K1: partials + fill rows [0, R). Roles write disjoint memory.
__global__ void __launch_bounds__(256)
prep_fill0_kernel(const float* __restrict__ h,
                  const float* __restrict__ W,
                  float4* __restrict__ out,
                  int N, int n4_0, int nPartBlks) {
    const int tid = threadIdx.x;
    const int bid = blockIdx.x;

    if (bid < nPartBlks) {
        const int warp = tid >> 5;
        const int lane = tid & 31;
        const int sub  = lane & 7;
        const int grp  = lane >> 3;
        const int node = bid * 32 + warp * 4 + grp;
        if (node < N) {
            const float* hp = h + (size_t)node * HDIM + sub * 16;
            const float* wp = W + sub * 16;
            float ad = 0.0f, as = 0.0f;
            #pragma unroll
            for (int k = 0; k < 4; k++) {
                const float4 hv = *reinterpret_cast<const float4*>(hp + k * 4);
                const float4 wd = *reinterpret_cast<const float4*>(wp + k * 4);
                const float4 ws = *reinterpret_cast<const float4*>(wp + HDIM + k * 4);
                ad += hv.x * wd.x + hv.y * wd.y + hv.z * wd.z + hv.w * wd.w;
                as += hv.x * ws.x + hv.y * ws.y + hv.z * ws.z + hv.w * ws.w;
            }
            #pragma unroll
            for (int o = 4; o; o >>= 1) {
                ad += __shfl_xor_sync(0xffffffffu, ad, o);
                as += __shfl_xor_sync(0xffffffffu, as, o);
            }
            if (sub == 0) g_p[node] = make_float2(ad, as);
        }
    } else {
        const int fbid = bid - nPartBlks;
        const float4 v = make_float4(NEGV, NEGV, NEGV, NEGV);
        const int base = fbid * 1024 + tid;
        #pragma unroll
        for (int k = 0; k < 4; k++) {
            int idx = base + k * 256;
            if (idx < n4_0) out[idx] = v;
        }
    }
}

// K2: fill rows [R, N) (blocks [0, nFill1)) + scatter edges with d < R (rest).
// Disjoint rows -> no intra-kernel ordering needed.
__global__ void __launch_bounds__(256)
fill1_scatter0_kernel(const int* __restrict__ sources,
                      const int* __restrict__ dests,
                      const float* __restrict__ weights,
                      const float* __restrict__ W,
                      const float* __restrict__ b,
                      float4* __restrict__ out4,
                      float* __restrict__ out,
                      int N, int E, int R, int n4_0, int n4_1, int nFill1) {
    const int tid = threadIdx.x;
    const int bid = blockIdx.x;

    if (bid < nFill1) {
        const float4 v = make_float4(NEGV, NEGV, NEGV, NEGV);
        const int base = bid * 1024 + tid;
        #pragma unroll
        for (int k = 0; k < 4; k++) {
            int idx = base + k * 256;
            if (idx < n4_1) out4[n4_0 + idx] = v;
        }
    } else {
        const int e = (bid - nFill1) * 256 + tid;
        if (e < E) {
            const int d = dests[e];
            if (d < R) {
                const int s = sources[e];
                const float2 pd = __ldg(&g_p[d]);
                const float2 ps = __ldg(&g_p[s]);
                const float val = pd.x + ps.y
                                + weights[e] * __ldg(W + 2 * HDIM) + __ldg(b);
                out[(size_t)d * N + s] = val;
            }
        }
    }
}

// K3: tail scatter for edges with d >= R. 512-thread blocks (one wave).
__global__ void __launch_bounds__(512)
scatter1_kernel(const int* __restrict__ sources,
                const int* __restrict__ dests,
                const float* __restrict__ weights,
                const float* __restrict__ W,
                const float* __restrict__ b,
                float* __restrict__ out, int E, int N, int R) {
    const int e = blockIdx.x * blockDim.x + threadIdx.x;
    if (e >= E) return;
    const int d = dests[e];
    if (d < R) return;
    const int s = sources[e];
    const float2 pd = __ldg(&g_p[d]);
    const float2 ps = __ldg(&g_p[s]);
    const float val = pd.x + ps.y + weights[e] * __ldg(W + 2 * HDIM) + __ldg(b);
    out[(size_t)d * N + s] = val;
}

extern "C" void kernel_launch(void* const* d_in, const int* in_sizes, int n_in,
                              void* d_out, int out_size) {
    const float* h       = (const float*)d_in[0];
    const int*   sources = (const int*)d_in[1];
    const int*   dests   = (const int*)d_in[2];
    const float* weights = (const float*)d_in[3];
    const float* W       = (const float*)d_in[4];
    const float* b       = (const float*)d_in[5];
    float* out = (float*)d_out;

    const int N = in_sizes[0] / HDIM;     // 12288
    const int E = in_sizes[1];            // 393216

    const int R = N - N / 6;              // 10240: rows in chunk0 (5/6)
    const int rowf4 = N / 4;              // float4s per row: 3072

    const int n4_0 = R * rowf4;           // chunk0 float4s: 31,457,280
    const int n4_1 = (N - R) * rowf4;     // chunk1 float4s:  6,291,456

    const int nPartBlks = (N + 31) / 32;              // 384
    const int nFill0    = (n4_0 + 1023) / 1024;       // 30,720
    const int nFill1    = (n4_1 + 1023) / 1024;       // 6,144
    const int nScatBlks = (E + 255) / 256;            // 1,536

    // K1: partials + fill chunk0
    prep_fill0_kernel<<<nPartBlks + nFill0, 256>>>(h, W, (float4*)out,
                                                   N, n4_0, nPartBlks);

    // K2: fill chunk1 + scatter into chunk0 (filled by K1 boundary)
    fill1_scatter0_kernel<<<nFill1 + nScatBlks, 256>>>(
        sources, dests, weights, W, b, (float4*)out, out,
        N, E, R, n4_0, n4_1, nFill1);

    // K3: tail scatter into chunk1
    scatter1_kernel<<<(E + 511) / 512, 512>>>(sources, dests, weights,
                                              W, b, out, E, N, R);
}

// round 11
// speedup vs baseline: 1.0084x; 1.0084x over previous
#include <cuda_runtime.h>
#include <cstddef>
#include <cstdint>

#define NEGV -1000000000.0f
#define HDIM 128
#define NMAX 12288
#define EMAX 393216
#define N_PART_BLKS 384
#define N_VALS_BLKS 192

// per-node partials: g_p[n].x = h[n].W[0:128), g_p[n].y = h[n].W[128:256)
__device__ float2 g_p[NMAX];
// packed per-edge result: {flat output index, value bits}
__device__ uint2  g_pack[EMAX];

// K1: partials + small fill chunk [0, n4a). Roles disjoint -> no ordering.
__global__ void __launch_bounds__(256)
k1_part_fill(const float* __restrict__ h,
             const float* __restrict__ W,
             float4* __restrict__ out,
             int N, int n4a) {
    const int tid = threadIdx.x;
    const int bid = blockIdx.x;

    if (bid < N_PART_BLKS) {
        // partials: 8 lanes/node, 4 nodes/warp, 32 nodes/block
        const int warp = tid >> 5;
        const int lane = tid & 31;
        const int sub  = lane & 7;
        const int grp  = lane >> 3;
        const int node = bid * 32 + warp * 4 + grp;
        if (node < N) {
            const float* hp = h + (size_t)node * HDIM + sub * 16;
            const float* wp = W + sub * 16;
            float ad = 0.0f, as = 0.0f;
            #pragma unroll
            for (int k = 0; k < 4; k++) {
                const float4 hv = *reinterpret_cast<const float4*>(hp + k * 4);
                const float4 wd = *reinterpret_cast<const float4*>(wp + k * 4);
                const float4 ws = *reinterpret_cast<const float4*>(wp + HDIM + k * 4);
                ad += hv.x * wd.x + hv.y * wd.y + hv.z * wd.z + hv.w * wd.w;
                as += hv.x * ws.x + hv.y * ws.y + hv.z * ws.z + hv.w * ws.w;
            }
            #pragma unroll
            for (int o = 4; o; o >>= 1) {
                ad += __shfl_xor_sync(0xffffffffu, ad, o);
                as += __shfl_xor_sync(0xffffffffu, as, o);
            }
            if (sub == 0) g_p[node] = make_float2(ad, as);
        }
    } else {
        const int fbid = bid - N_PART_BLKS;
        const float4 v = make_float4(NEGV, NEGV, NEGV, NEGV);
        const int base = fbid * 1024 + tid;
        #pragma unroll
        for (int k = 0; k < 4; k++) {
            int idx = base + k * 256;
            if (idx < n4a) out[idx] = v;
        }
    }
}

// K2: vals blocks (write g_pack; read g_p from K1 boundary) + fill rest.
// Roles write disjoint memory -> no intra-kernel ordering.
__global__ void __launch_bounds__(256)
k2_vals_fill(const int* __restrict__ sources,
             const int* __restrict__ dests,
             const float* __restrict__ weights,
             const float* __restrict__ W,
             const float* __restrict__ b,
             float4* __restrict__ out,
             int N, int E, int n4a, int n4b) {
    const int tid = threadIdx.x;
    const int bid = blockIdx.x;

    if (bid < N_VALS_BLKS) {
        const float wW = __ldg(W + 2 * HDIM);
        const float bb = __ldg(b);
        const int stride = N_VALS_BLKS * 256;
        for (int e = bid * 256 + tid; e < E; e += stride) {
            const int s = sources[e];
            const int d = dests[e];
            const float2 pd = __ldg(&g_p[d]);
            const float2 ps = __ldg(&g_p[s]);
            const float val = pd.x + ps.y + weights[e] * wW + bb;
            g_pack[e] = make_uint2((uint32_t)d * (uint32_t)N + (uint32_t)s,
                                   __float_as_uint(val));
        }
    } else {
        const int fbid = bid - N_VALS_BLKS;
        const float4 v = make_float4(NEGV, NEGV, NEGV, NEGV);
        const int base = fbid * 1024 + tid;
        #pragma unroll
        for (int k = 0; k < 4; k++) {
            int idx = base + k * 256;
            if (idx < n4b) out[n4a + idx] = v;
        }
    }
}

// K3: pure scatter — one coalesced 8B load, one random 4B store.
__global__ void __launch_bounds__(256)
k3_scatter(float* __restrict__ out, int E) {
    const int e = blockIdx.x * blockDim.x + threadIdx.x;
    if (e < E) {
        const uint2 p = g_pack[e];
        out[p.x] = __uint_as_float(p.y);
    }
}

extern "C" void kernel_launch(void* const* d_in, const int* in_sizes, int n_in,
                              void* d_out, int out_size) {
    const float* h       = (const float*)d_in[0];
    const int*   sources = (const int*)d_in[1];
    const int*   dests   = (const int*)d_in[2];
    const float* weights = (const float*)d_in[3];
    const float* W       = (const float*)d_in[4];
    const float* b       = (const float*)d_in[5];
    float* out = (float*)d_out;

    const int N = in_sizes[0] / HDIM;     // 12288
    const int E = in_sizes[1];            // 393216

    long long total = (long long)N * N;
    const int n4 = (int)(total >> 2);     // 37,748,736

    // K1 fill chunk sized ~= partials duration (2304 blocks ~ 5.4us of stores)
    const int nFillA = 2304;
    const int n4a = nFillA * 1024;        // 2,359,296
    const int n4b = n4 - n4a;             // 35,389,440
    const int nFillB = (n4b + 1023) / 1024;   // 34,560

    k1_part_fill<<<N_PART_BLKS + nFillA, 256>>>(h, W, (float4*)out, N, n4a);

    k2_vals_fill<<<N_VALS_BLKS + nFillB, 256>>>(sources, dests, weights, W, b,
                                                (float4*)out, N, E, n4a, n4b);

    k3_scatter<<<(E + 255) / 256, 256>>>(out, E);
}

// round 12
// speedup vs baseline: 1.0175x; 1.0090x over previous
#include <cuda_runtime.h>
#include <cstddef>
#include <cstdint>

#define NEGV -1000000000.0f
#define HDIM 128
#define NMAX 12288
#define EMAX 393216
#define N_PART_BLKS 384
#define N_VALS_BLKS 192

__device__ float2 g_p[NMAX];    // per-node partials
__device__ uint2  g_pack[EMAX]; // per-edge {flat index, value bits}

__device__ __forceinline__ void pdl_trigger() {
    asm volatile("griddepcontrol.launch_dependents;" ::: "memory");
}
__device__ __forceinline__ void pdl_wait() {
    asm volatile("griddepcontrol.wait;" ::: "memory");
}

// K1: node partials only. Triggers dependents immediately so K2's fill
// blocks start while partials run.
__global__ void __launch_bounds__(256)
k1_partials(const float* __restrict__ h,
            const float* __restrict__ W,
            int N) {
    pdl_trigger();
    const int tid  = threadIdx.x;
    const int warp = tid >> 5;
    const int lane = tid & 31;
    const int sub  = lane & 7;
    const int grp  = lane >> 3;
    const int node = blockIdx.x * 32 + warp * 4 + grp;
    if (node < N) {
        const float* hp = h + (size_t)node * HDIM + sub * 16;
        const float* wp = W + sub * 16;
        float ad = 0.0f, as = 0.0f;
        #pragma unroll
        for (int k = 0; k < 4; k++) {
            const float4 hv = *reinterpret_cast<const float4*>(hp + k * 4);
            const float4 wd = *reinterpret_cast<const float4*>(wp + k * 4);
            const float4 ws = *reinterpret_cast<const float4*>(wp + HDIM + k * 4);
            ad += hv.x * wd.x + hv.y * wd.y + hv.z * wd.z + hv.w * wd.w;
            as += hv.x * ws.x + hv.y * ws.y + hv.z * ws.z + hv.w * ws.w;
        }
        #pragma unroll
        for (int o = 4; o; o >>= 1) {
            ad += __shfl_xor_sync(0xffffffffu, ad, o);
            as += __shfl_xor_sync(0xffffffffu, as, o);
        }
        if (sub == 0) g_p[node] = make_float2(ad, as);
    }
}

// K2: vals blocks (PDL-wait on K1, then pack edge results) + fill blocks
// (no wait — disjoint from g_p, start immediately).
__global__ void __launch_bounds__(256)
k2_vals_fill(const int* __restrict__ sources,
             const int* __restrict__ dests,
             const float* __restrict__ weights,
             const float* __restrict__ W,
             const float* __restrict__ b,
             float4* __restrict__ out,
             int N, int E, int n4) {
    pdl_trigger();
    const int tid = threadIdx.x;
    const int bid = blockIdx.x;

    if (bid < N_VALS_BLKS) {
        pdl_wait();   // g_p ready only after K1's grid completes
        const float wW = __ldg(W + 2 * HDIM);
        const float bb = __ldg(b);
        const int stride = N_VALS_BLKS * 256;
        for (int e = bid * 256 + tid; e < E; e += stride) {
            const int s = sources[e];
            const int d = dests[e];
            const float2 pd = __ldg(&g_p[d]);
            const float2 ps = __ldg(&g_p[s]);
            const float val = pd.x + ps.y + weights[e] * wW + bb;
            g_pack[e] = make_uint2((uint32_t)d * (uint32_t)N + (uint32_t)s,
                                   __float_as_uint(val));
        }
    } else {
        const int fbid = bid - N_VALS_BLKS;
        const float4 v = make_float4(NEGV, NEGV, NEGV, NEGV);
        const int base = fbid * 1024 + tid;
        #pragma unroll
        for (int k = 0; k < 4; k++) {
            int idx = base + k * 256;
            if (idx < n4) out[idx] = v;
        }
    }
}

// K3: pure scatter. PDL-wait for K2 (fill + vals), then one coalesced 8B
// load and one random 4B store per edge.
__global__ void __launch_bounds__(256)
k3_scatter(float* __restrict__ out, int E) {
    pdl_wait();
    const int e = blockIdx.x * blockDim.x + threadIdx.x;
    if (e < E) {
        const uint2 p = g_pack[e];
        out[p.x] = __uint_as_float(p.y);
    }
}

static void launch_pdl(void* func, dim3 grid, dim3 block,
                       void** args) {
    cudaLaunchConfig_t cfg = {};
    cfg.gridDim = grid;
    cfg.blockDim = block;
    cfg.dynamicSmemBytes = 0;
    cfg.stream = 0;
    cudaLaunchAttribute attr[1];
    attr[0].id = cudaLaunchAttributeProgrammaticStreamSerialization;
    attr[0].val.programmaticStreamSerializationAllowed = 1;
    cfg.attrs = attr;
    cfg.numAttrs = 1;
    cudaLaunchKernelExC(&cfg, func, args);
}

extern "C" void kernel_launch(void* const* d_in, const int* in_sizes, int n_in,
                              void* d_out, int out_size) {
    const float* h       = (const float*)d_in[0];
    const int*   sources = (const int*)d_in[1];
    const int*   dests   = (const int*)d_in[2];
    const float* weights = (const float*)d_in[3];
    const float* W       = (const float*)d_in[4];
    const float* b       = (const float*)d_in[5];
    float* out = (float*)d_out;

    int N = in_sizes[0] / HDIM;     // 12288
    int E = in_sizes[1];            // 393216

    long long total = (long long)N * N;
    int n4 = (int)(total >> 2);     // 37,748,736

    // K1: partials (primary; plain launch)
    k1_partials<<<N_PART_BLKS, 256>>>(h, W, N);

    // K2: vals + fill (PDL secondary of K1)
    {
        const int nFillBlks = (n4 + 1023) / 1024;   // 36,864
        float4* out4 = (float4*)out;
        void* args[] = { (void*)&sources, (void*)&dests, (void*)&weights,
                         (void*)&W, (void*)&b, (void*)&out4,
                         (void*)&N, (void*)&E, (void*)&n4 };
        launch_pdl((void*)k2_vals_fill,
                   dim3(N_VALS_BLKS + nFillBlks), dim3(256), args);
    }

    // K3: scatter (PDL secondary of K2)
    {
        void* args[] = { (void*)&out, (void*)&E };
        launch_pdl((void*)k3_scatter,
                   dim3((E + 255) / 256), dim3(256), args);
    }
}